// round 5
// baseline (speedup 1.0000x reference)
#include <cuda_runtime.h>
#include <math.h>

#define Bc 4
#define Lc 256
#define Ec 128
#define Hc 8
#define Dh 16
#define NUc 512
#define NTc 256

// ---------------- scratch (device globals; no allocation) ----------------
__device__ float g_q_uu[Bc*Lc*Ec];
__device__ float g_q_ta[Bc*Lc*Ec];
__device__ float g_q_du[Bc*Lc*Ec];
__device__ float g_k_ta[Bc*NTc*Ec];   // head-blocked [b][h][n][16]
__device__ float g_v_ta[Bc*NTc*Ec];
__device__ float g_k_du[Bc*Lc*Ec];
__device__ float g_v_du[Bc*Lc*Ec];
__device__ float g_kb_uu[Bc*NUc*Ec];
__device__ float g_vb_uu[Bc*NUc*Ec];
__device__ float g_ciT[Bc*2*Lc*NUc];  // [b][j][n]
__device__ float g_o_uu[Bc*Lc*Ec];
__device__ float g_o_ta[Bc*Lc*Ec];
__device__ float g_o_du[Bc*Lc*Ec];
__device__ float g_WR[3][Ec*Ec];      // combined weights, row-major [seg][e][j]
__device__ float g_bcomb[Ec];
__device__ float g_y[Bc*Lc*Ec];
__device__ float g_part[32][2][Ec];
__device__ float g_mean[Ec];
__device__ float g_rstd[Ec];

// ---------------- combined output projection weights, row-major ----------------
// g_WR[m][e][j] = sum_k dim_w[e, m*128+k] * ow_m[k, j]
__global__ void combine_w2(const float* __restrict__ dim_w,
                           const float* __restrict__ uu_ow,
                           const float* __restrict__ ta_ow,
                           const float* __restrict__ du_ow)
{
    int m = blockIdx.z;
    const float* ow = (m == 0) ? uu_ow : (m == 1) ? ta_ow : du_ow;
    float* dst = g_WR[m];
    int j0 = blockIdx.x * 32, e0 = blockIdx.y * 32;
    int tx = threadIdx.x, ty = threadIdx.y;

    __shared__ float dws[32][33];   // [e_local][k_local]
    __shared__ float ows[32][33];   // [k_local][j_local]
    float acc[4] = {0.f, 0.f, 0.f, 0.f};
    for (int k0 = 0; k0 < Ec; k0 += 32) {
        #pragma unroll
        for (int r = 0; r < 4; r++) {
            int row = ty + 8 * r;
            dws[row][tx] = dim_w[(size_t)(e0 + row) * (3 * Ec) + m * Ec + k0 + tx];
            ows[row][tx] = ow[(size_t)(k0 + row) * Ec + j0 + tx];
        }
        __syncthreads();
        #pragma unroll
        for (int kk = 0; kk < 32; kk++) {
            float o = ows[kk][tx];
            #pragma unroll
            for (int r = 0; r < 4; r++) acc[r] += dws[ty + 8 * r][kk] * o;
        }
        __syncthreads();
    }
    #pragma unroll
    for (int r = 0; r < 4; r++)
        dst[(size_t)(e0 + ty + 8 * r) * Ec + j0 + tx] = acc[r];
}

// bias: bcomb[e] = dim_b[e] + sum_k dim_w[e,k] * cat(ob)[k]
__global__ void combine_b(const float* __restrict__ dim_w, const float* __restrict__ dim_b,
                          const float* __restrict__ uu_ob, const float* __restrict__ ta_ob,
                          const float* __restrict__ du_ob)
{
    int warp = threadIdx.x >> 5, lane = threadIdx.x & 31;
    for (int e = warp; e < Ec; e += 4) {
        float s = 0.f;
        #pragma unroll
        for (int i = 0; i < 12; i++) {
            int k = lane + 32 * i;
            const float* ob = (i < 4) ? uu_ob : (i < 8) ? ta_ob : du_ob;
            int kl = k - (i < 4 ? 0 : (i < 8 ? Ec : 2 * Ec));
            s += dim_w[(size_t)e * (3 * Ec) + k] * ob[kl];
        }
        #pragma unroll
        for (int o = 16; o >= 1; o >>= 1) s += __shfl_xor_sync(0xffffffffu, s, o);
        if (lane == 0) g_bcomb[e] = dim_b[e] + s;
    }
}

// ---------------- transpose CI: [B][NU][2L] -> [B][2L][NU] ----------------
__global__ void ci_transpose(const float* __restrict__ CI)
{
    __shared__ float t[32][33];
    int n0 = blockIdx.x * 32, j0 = blockIdx.y * 32, b = blockIdx.z;
    int tx = threadIdx.x, ty = threadIdx.y;
    #pragma unroll
    for (int r = 0; r < 4; r++) {
        int n = n0 + ty + 8 * r;
        t[ty + 8 * r][tx] = CI[((size_t)b * NUc + n) * (2 * Lc) + j0 + tx];
    }
    __syncthreads();
    #pragma unroll
    for (int r = 0; r < 4; r++) {
        int j = j0 + ty + 8 * r;
        g_ciT[((size_t)b * 2 * Lc + j) * NUc + n0 + tx] = t[tx][ty + 8 * r];
    }
}

// ---------------- input projections: 64x64 tiles, 4x4 outputs/thread ----------------
__global__ void __launch_bounds__(256) proj_all(
    const float* __restrict__ UU, const float* __restrict__ DU,
    const float* __restrict__ TA,
    const float* __restrict__ uu_iw, const float* __restrict__ uu_ib,
    const float* __restrict__ ta_iw, const float* __restrict__ ta_ib,
    const float* __restrict__ du_iw, const float* __restrict__ du_ib)
{
    const float *X, *W, *bias;
    float* out;
    int K = Ec, sx = Ec, M = Bc * Lc, R = 0;
    switch (blockIdx.z) {
        case 0: X = DU; W = uu_iw;               bias = uu_ib;           out = g_q_uu;  break;
        case 1: X = DU; W = ta_iw;               bias = ta_ib;           out = g_q_ta;  break;
        case 2: X = DU; W = du_iw;               bias = du_ib;           out = g_q_du;  break;
        case 3: X = TA; W = ta_iw + Ec * Ec;     bias = ta_ib + Ec;      out = g_k_ta;  R = NTc; break;
        case 4: X = TA; W = ta_iw + 2 * Ec * Ec; bias = ta_ib + 2 * Ec;  out = g_v_ta;  R = NTc; break;
        case 5: X = DU; W = du_iw + Ec * Ec;     bias = du_ib + Ec;      out = g_k_du;  R = Lc;  break;
        case 6: X = DU; W = du_iw + 2 * Ec * Ec; bias = du_ib + 2 * Ec;  out = g_v_du;  R = Lc;  break;
        case 7: X = UU; W = uu_iw + Ec * Ec;     bias = uu_ib + Ec;      out = g_kb_uu;
                K = Ec - 2; sx = Ec - 2; M = Bc * NUc; R = NUc; break;
        default: X = UU; W = uu_iw + 2 * Ec * Ec; bias = uu_ib + 2 * Ec; out = g_vb_uu;
                K = Ec - 2; sx = Ec - 2; M = Bc * NUc; R = NUc; break;
    }
    int m0 = blockIdx.y * 64;
    if (m0 >= M) return;
    int n0 = blockIdx.x * 64;
    int tx = threadIdx.x, ty = threadIdx.y;          // 16 x 16
    int tid = ty * 16 + tx;
    int lrow = tid >> 5, lcol = tid & 31;

    __shared__ float Xs[64][33];
    __shared__ float Ws[64][33];
    float acc[4][4];
    #pragma unroll
    for (int i = 0; i < 4; i++)
        #pragma unroll
        for (int j = 0; j < 4; j++) acc[i][j] = 0.f;

    for (int k0 = 0; k0 < K; k0 += 32) {
        int k = k0 + lcol;
        bool kin = (k < K);
        #pragma unroll
        for (int i = 0; i < 8; i++) {
            int row = lrow + 8 * i;
            Xs[row][lcol] = kin ? X[(size_t)(m0 + row) * sx + k] : 0.f;
            Ws[row][lcol] = kin ? W[(size_t)(n0 + row) * Ec + k] : 0.f;
        }
        __syncthreads();
        #pragma unroll
        for (int kk = 0; kk < 32; kk++) {
            float a[4], w[4];
            #pragma unroll
            for (int i = 0; i < 4; i++) a[i] = Xs[ty + 16 * i][kk];
            #pragma unroll
            for (int j = 0; j < 4; j++) w[j] = Ws[tx + 16 * j][kk];
            #pragma unroll
            for (int i = 0; i < 4; i++)
                #pragma unroll
                for (int j = 0; j < 4; j++) acc[i][j] += a[i] * w[j];
        }
        __syncthreads();
    }
    #pragma unroll
    for (int j = 0; j < 4; j++) {
        int n = n0 + tx + 16 * j;
        float bv = bias[n];
        #pragma unroll
        for (int i = 0; i < 4; i++) {
            int m = m0 + ty + 16 * i;
            float v = acc[i][j] + bv;
            if (R == 0) {
                out[(size_t)m * Ec + n] = v;
            } else {
                int bb = m / R, row = m % R;
                out[(((size_t)bb * Hc + (n >> 4)) * R + row) * Dh + (n & 15)] = v;
            }
        }
    }
}

__device__ __forceinline__ float wred_sum(float v) {
    #pragma unroll
    for (int o = 16; o >= 1; o >>= 1) v += __shfl_xor_sync(0xffffffffu, v, o);
    return v;
}
__device__ __forceinline__ float wred_max(float v) {
    #pragma unroll
    for (int o = 16; o >= 1; o >>= 1) v = fmaxf(v, __shfl_xor_sync(0xffffffffu, v, o));
    return v;
}

// ---------------- attention: reused SMEM buffer, 4 queries/warp ----------------
template<int NK, bool IS_UU>
__global__ void __launch_bounds__(128, 3) attn3(const float* __restrict__ inw)
{
    constexpr int NPL = NK / 32;
    extern __shared__ float4 sm4[];   // [NK][5] float4 rows (pad 20 floats)

    const float *Q, *Kb, *Vb;
    float* O;
    int b;
    if constexpr (IS_UU) {
        b = blockIdx.z;
        Q = g_q_uu; Kb = g_kb_uu; Vb = g_vb_uu; O = g_o_uu;
    } else {
        if (blockIdx.z < Bc) { b = blockIdx.z;      Q = g_q_ta; Kb = g_k_ta; Vb = g_v_ta; O = g_o_ta; }
        else                 { b = blockIdx.z - Bc; Q = g_q_du; Kb = g_k_du; Vb = g_v_du; O = g_o_du; }
    }
    int h = blockIdx.y, lt = blockIdx.x;
    int tid = threadIdx.x, warp = tid >> 5, lane = tid & 31;

    const float4* ksrc = (const float4*)(Kb + ((size_t)(b * Hc + h) * NK) * Dh);
    const float4* vsrc = (const float4*)(Vb + ((size_t)(b * Hc + h) * NK) * Dh);

    for (int i = tid; i < NK * 4; i += 128) sm4[(i >> 2) * 5 + (i & 3)] = ksrc[i];
    __syncthreads();

    int l0 = lt * 16 + warp * 4;
    int bl0 = b * Lc + l0;

    float q[4][16];
    #pragma unroll
    for (int qi = 0; qi < 4; qi++) {
        const float4* qp = (const float4*)(Q + (size_t)(bl0 + qi) * Ec + h * Dh);
        #pragma unroll
        for (int j = 0; j < 4; j++) {
            float4 t = qp[j];
            q[qi][j*4+0] = t.x; q[qi][j*4+1] = t.y; q[qi][j*4+2] = t.z; q[qi][j*4+3] = t.w;
        }
    }

    float c1k[4], c2k[4];
    const float *cp1[4], *cp2[4];
    if constexpr (IS_UU) {
        #pragma unroll
        for (int qi = 0; qi < 4; qi++) { c1k[qi] = 0.f; c2k[qi] = 0.f; }
        #pragma unroll
        for (int d = 0; d < 16; d++) {
            size_t kr = (size_t)(Ec + h * Dh + d) * Ec;
            float w1 = __ldg(inw + kr + 126), w2 = __ldg(inw + kr + 127);
            #pragma unroll
            for (int qi = 0; qi < 4; qi++) { c1k[qi] += q[qi][d] * w1; c2k[qi] += q[qi][d] * w2; }
        }
        #pragma unroll
        for (int qi = 0; qi < 4; qi++) {
            cp1[qi] = g_ciT + ((size_t)b * 2 * Lc + (l0 + qi)) * NUc;
            cp2[qi] = cp1[qi] + (size_t)Lc * NUc;
        }
    }

    float sv[4][NPL];
    float mx[4] = {-1e30f, -1e30f, -1e30f, -1e30f};
    #pragma unroll
    for (int i = 0; i < NPL; i++) {
        int n = i * 32 + lane;
        const float4* kr = sm4 + n * 5;
        float4 k0 = kr[0], k1 = kr[1], k2 = kr[2], k3 = kr[3];
        #pragma unroll
        for (int qi = 0; qi < 4; qi++) {
            float s = q[qi][0]*k0.x + q[qi][1]*k0.y + q[qi][2]*k0.z + q[qi][3]*k0.w
                    + q[qi][4]*k1.x + q[qi][5]*k1.y + q[qi][6]*k1.z + q[qi][7]*k1.w
                    + q[qi][8]*k2.x + q[qi][9]*k2.y + q[qi][10]*k2.z + q[qi][11]*k2.w
                    + q[qi][12]*k3.x + q[qi][13]*k3.y + q[qi][14]*k3.z + q[qi][15]*k3.w;
            if constexpr (IS_UU) s += cp1[qi][n] * c1k[qi] + cp2[qi][n] * c2k[qi];
            s *= 0.25f;
            sv[qi][i] = s;
            mx[qi] = fmaxf(mx[qi], s);
        }
    }
    float invsum[4];
    #pragma unroll
    for (int qi = 0; qi < 4; qi++) {
        float m = wred_max(mx[qi]);
        float sum = 0.f;
        #pragma unroll
        for (int i = 0; i < NPL; i++) { sv[qi][i] = __expf(sv[qi][i] - m); sum += sv[qi][i]; }
        invsum[qi] = 1.f / wred_sum(sum);
    }

    __syncthreads();
    for (int i = tid; i < NK * 4; i += 128) sm4[(i >> 2) * 5 + (i & 3)] = vsrc[i];
    __syncthreads();

    float a[4][16];
    #pragma unroll
    for (int qi = 0; qi < 4; qi++)
        #pragma unroll
        for (int d = 0; d < 16; d++) a[qi][d] = 0.f;
    float A1[4] = {0.f,0.f,0.f,0.f}, A2[4] = {0.f,0.f,0.f,0.f};
    #pragma unroll
    for (int i = 0; i < NPL; i++) {
        int n = i * 32 + lane;
        const float4* vr = sm4 + n * 5;
        float4 v0 = vr[0], v1 = vr[1], v2 = vr[2], v3 = vr[3];
        #pragma unroll
        for (int qi = 0; qi < 4; qi++) {
            float p = sv[qi][i];
            a[qi][0] += p*v0.x;  a[qi][1] += p*v0.y;  a[qi][2] += p*v0.z;  a[qi][3] += p*v0.w;
            a[qi][4] += p*v1.x;  a[qi][5] += p*v1.y;  a[qi][6] += p*v1.z;  a[qi][7] += p*v1.w;
            a[qi][8] += p*v2.x;  a[qi][9] += p*v2.y;  a[qi][10]+= p*v2.z;  a[qi][11]+= p*v2.w;
            a[qi][12]+= p*v3.x;  a[qi][13]+= p*v3.y;  a[qi][14]+= p*v3.z;  a[qi][15]+= p*v3.w;
            if constexpr (IS_UU) { A1[qi] += p * cp1[qi][n]; A2[qi] += p * cp2[qi][n]; }
        }
    }
    #pragma unroll
    for (int qi = 0; qi < 4; qi++) {
        #pragma unroll
        for (int d = 0; d < 16; d++) a[qi][d] = wred_sum(a[qi][d]);
        if constexpr (IS_UU) { A1[qi] = wred_sum(A1[qi]); A2[qi] = wred_sum(A2[qi]); }
        if (lane == 0) {
            float inv = invsum[qi];
            float o16[16];
            #pragma unroll
            for (int d = 0; d < 16; d++) {
                float v = a[qi][d];
                if constexpr (IS_UU) {
                    size_t vr = (size_t)(2 * Ec + h * Dh + d) * Ec;
                    v += A1[qi] * __ldg(inw + vr + 126) + A2[qi] * __ldg(inw + vr + 127);
                }
                o16[d] = v * inv;
            }
            float4* op = (float4*)(O + (size_t)(bl0 + qi) * Ec + h * Dh);
            op[0] = make_float4(o16[0], o16[1], o16[2], o16[3]);
            op[1] = make_float4(o16[4], o16[5], o16[6], o16[7]);
            op[2] = make_float4(o16[8], o16[9], o16[10], o16[11]);
            op[3] = make_float4(o16[12], o16[13], o16[14], o16[15]);
        }
    }
}

// ---------------- final projection GEMM: y[1024,128] = cat(o)[1024,384] @ Wcat^T + b ----------------
__global__ void __launch_bounds__(256) final_gemm()
{
    int m0 = blockIdx.y * 64, n0 = blockIdx.x * 64;
    int tx = threadIdx.x, ty = threadIdx.y;
    int tid = ty * 16 + tx;
    int lrow = tid >> 5, lcol = tid & 31;

    __shared__ float Xs[64][33];
    __shared__ float Ws[64][33];
    float acc[4][4];
    #pragma unroll
    for (int i = 0; i < 4; i++)
        #pragma unroll
        for (int j = 0; j < 4; j++) acc[i][j] = 0.f;

    for (int k0 = 0; k0 < 3 * Ec; k0 += 32) {
        int seg = k0 >> 7, kl0 = k0 & 127;
        const float* X = (seg == 0) ? g_o_uu : (seg == 1) ? g_o_ta : g_o_du;
        const float* W = g_WR[seg];
        #pragma unroll
        for (int i = 0; i < 8; i++) {
            int row = lrow + 8 * i;
            Xs[row][lcol] = X[(size_t)(m0 + row) * Ec + kl0 + lcol];
            Ws[row][lcol] = W[(size_t)(n0 + row) * Ec + kl0 + lcol];
        }
        __syncthreads();
        #pragma unroll
        for (int kk = 0; kk < 32; kk++) {
            float a[4], w[4];
            #pragma unroll
            for (int i = 0; i < 4; i++) a[i] = Xs[ty + 16 * i][kk];
            #pragma unroll
            for (int j = 0; j < 4; j++) w[j] = Ws[tx + 16 * j][kk];
            #pragma unroll
            for (int i = 0; i < 4; i++)
                #pragma unroll
                for (int j = 0; j < 4; j++) acc[i][j] += a[i] * w[j];
        }
        __syncthreads();
    }
    #pragma unroll
    for (int j = 0; j < 4; j++) {
        int n = n0 + tx + 16 * j;
        float bv = g_bcomb[n];
        #pragma unroll
        for (int i = 0; i < 4; i++) {
            int m = m0 + ty + 16 * i;
            g_y[(size_t)m * Ec + n] = acc[i][j] + bv;
        }
    }
}

// ---------------- batchnorm: 32-CTA partial sums + finalize ----------------
__global__ void bn_partial()
{
    int c = blockIdx.x;                 // 32 chunks of 32 rows
    int t = threadIdx.x;                // 256 = 2 x 128
    int e = t & (Ec - 1), half = t >> 7;
    float s = 0.f, s2 = 0.f;
    int r0 = c * 32 + half * 16;
    for (int r = r0; r < r0 + 16; r++) {
        float v = g_y[(size_t)r * Ec + e];
        s += v; s2 += v * v;
    }
    __shared__ float sh[2][2][Ec];
    sh[half][0][e] = s; sh[half][1][e] = s2;
    __syncthreads();
    if (half == 0) {
        g_part[c][0][e] = sh[0][0][e] + sh[1][0][e];
        g_part[c][1][e] = sh[0][1][e] + sh[1][1][e];
    }
}

__global__ void bn_finalize()
{
    int e = threadIdx.x;
    float S = 0.f, S2 = 0.f;
    #pragma unroll
    for (int c = 0; c < 32; c++) { S += g_part[c][0][e]; S2 += g_part[c][1][e]; }
    float mean = S / (Bc * Lc);
    float var = S2 / (Bc * Lc) - mean * mean;
    g_mean[e] = mean;
    g_rstd[e] = rsqrtf(var + 1e-5f);
}

__global__ void bn_apply(const float* __restrict__ gamma, const float* __restrict__ beta,
                         float* __restrict__ out)
{
    int i = blockIdx.x * 256 + threadIdx.x;
    int e = i & (Ec - 1);
    float v = (g_y[i] - g_mean[e]) * g_rstd[e] * gamma[e] + beta[e];
    out[i] = fmaxf(v, 0.f);
}

extern "C" void kernel_launch(void* const* d_in, const int* in_sizes, int n_in,
                              void* d_out, int out_size)
{
    const float* UUMat   = (const float*)d_in[0];
    const float* DUMat   = (const float*)d_in[1];
    const float* TAMat   = (const float*)d_in[2];
    const float* CIMat   = (const float*)d_in[3];
    const float* uu_in_w = (const float*)d_in[4];
    const float* uu_in_b = (const float*)d_in[5];
    const float* uu_out_w= (const float*)d_in[6];
    const float* uu_out_b= (const float*)d_in[7];
    const float* ta_in_w = (const float*)d_in[8];
    const float* ta_in_b = (const float*)d_in[9];
    const float* ta_out_w= (const float*)d_in[10];
    const float* ta_out_b= (const float*)d_in[11];
    const float* du_in_w = (const float*)d_in[12];
    const float* du_in_b = (const float*)d_in[13];
    const float* du_out_w= (const float*)d_in[14];
    const float* du_out_b= (const float*)d_in[15];
    const float* dim_w   = (const float*)d_in[16];
    const float* dim_b   = (const float*)d_in[17];
    const float* bn_gamma= (const float*)d_in[18];
    const float* bn_beta = (const float*)d_in[19];
    float* out = (float*)d_out;

    combine_w2<<<dim3(4, 4, 3), dim3(32, 8)>>>(dim_w, uu_out_w, ta_out_w, du_out_w);
    combine_b<<<1, 128>>>(dim_w, dim_b, uu_out_b, ta_out_b, du_out_b);

    ci_transpose<<<dim3(NUc / 32, 2 * Lc / 32, Bc), dim3(32, 8)>>>(CIMat);

    proj_all<<<dim3(2, 32, 9), dim3(16, 16)>>>(
        UUMat, DUMat, TAMat, uu_in_w, uu_in_b, ta_in_w, ta_in_b, du_in_w, du_in_b);

    attn3<NUc, true><<<dim3(Lc / 16, Hc, Bc), 128, NUc * 5 * sizeof(float4)>>>(uu_in_w);
    attn3<NTc, false><<<dim3(Lc / 16, Hc, 2 * Bc), 128, NTc * 5 * sizeof(float4)>>>(nullptr);

    final_gemm<<<dim3(2, 16), dim3(16, 16)>>>();
    bn_partial<<<32, 256>>>();
    bn_finalize<<<1, 128>>>();
    bn_apply<<<(Bc * Lc * Ec) / 256, 256>>>(bn_gamma, bn_beta, out);
}

// round 6
// speedup vs baseline: 1.1346x; 1.1346x over previous
#include <cuda_runtime.h>
#include <math.h>

#define Bc 4
#define Lc 256
#define Ec 128
#define Hc 8
#define Dh 16
#define NUc 512
#define NTc 256

// ---------------- scratch (device globals; no allocation) ----------------
__device__ float g_q_uu[Bc*Lc*Ec];
__device__ float g_q_ta[Bc*Lc*Ec];
__device__ float g_q_du[Bc*Lc*Ec];
__device__ float g_k_ta[Bc*NTc*Ec];   // head-blocked [b][h][n][16]
__device__ float g_v_ta[Bc*NTc*Ec];
__device__ float g_k_du[Bc*Lc*Ec];
__device__ float g_v_du[Bc*Lc*Ec];
__device__ float g_kb_uu[Bc*NUc*Ec];
__device__ float g_vb_uu[Bc*NUc*Ec];
__device__ float g_ciT[Bc*2*Lc*NUc];  // [b][j][n]
__device__ float g_o_uu[Bc*Lc*Ec];
__device__ float g_o_ta[Bc*Lc*Ec];
__device__ float g_o_du[Bc*Lc*Ec];
__device__ float g_WR[3][Ec*Ec];      // combined weights, row-major [seg][e][j]
__device__ float g_bcomb[Ec];
__device__ float g_y[Bc*Lc*Ec];
__device__ float g_part[16][2][Ec];   // per-row-tile channel sums / sumsq
__device__ float g_mean[Ec];
__device__ float g_rstd[Ec];

// =================== stage 1: fused prep ===================
// blocks [0,48): combine_w   | block 48: combine_b
// blocks [49,1073): ci_transpose | blocks [1073,1649): proj_all

__device__ void combine_w_body(float* sbuf, int id, int t,
                               const float* __restrict__ dim_w,
                               const float* __restrict__ uu_ow,
                               const float* __restrict__ ta_ow,
                               const float* __restrict__ du_ow)
{
    int bx = id & 3, by = (id >> 2) & 3, m = id >> 4;
    const float* ow = (m == 0) ? uu_ow : (m == 1) ? ta_ow : du_ow;
    float* dst = g_WR[m];
    int j0 = bx * 32, e0 = by * 32;
    int tx = t & 31, ty = t >> 5;
    float (*dws)[33] = (float(*)[33])sbuf;          // [32][33]
    float (*ows)[33] = (float(*)[33])(sbuf + 32*33);

    float acc[4] = {0.f, 0.f, 0.f, 0.f};
    for (int k0 = 0; k0 < Ec; k0 += 32) {
        #pragma unroll
        for (int r = 0; r < 4; r++) {
            int row = ty + 8 * r;
            dws[row][tx] = dim_w[(size_t)(e0 + row) * (3 * Ec) + m * Ec + k0 + tx];
            ows[row][tx] = ow[(size_t)(k0 + row) * Ec + j0 + tx];
        }
        __syncthreads();
        #pragma unroll
        for (int kk = 0; kk < 32; kk++) {
            float o = ows[kk][tx];
            #pragma unroll
            for (int r = 0; r < 4; r++) acc[r] += dws[ty + 8 * r][kk] * o;
        }
        __syncthreads();
    }
    #pragma unroll
    for (int r = 0; r < 4; r++)
        dst[(size_t)(e0 + ty + 8 * r) * Ec + j0 + tx] = acc[r];
}

__device__ void combine_b_body(int t,
                               const float* __restrict__ dim_w, const float* __restrict__ dim_b,
                               const float* __restrict__ uu_ob, const float* __restrict__ ta_ob,
                               const float* __restrict__ du_ob)
{
    int warp = t >> 5, lane = t & 31;
    for (int e = warp; e < Ec; e += 4) {
        float s = 0.f;
        #pragma unroll
        for (int i = 0; i < 12; i++) {
            int k = lane + 32 * i;
            const float* ob = (i < 4) ? uu_ob : (i < 8) ? ta_ob : du_ob;
            int kl = k - (i < 4 ? 0 : (i < 8 ? Ec : 2 * Ec));
            s += dim_w[(size_t)e * (3 * Ec) + k] * ob[kl];
        }
        #pragma unroll
        for (int o = 16; o >= 1; o >>= 1) s += __shfl_xor_sync(0xffffffffu, s, o);
        if (lane == 0) g_bcomb[e] = dim_b[e] + s;
    }
}

__device__ void ci_body(float* sbuf, int id, int t, const float* __restrict__ CI)
{
    float (*tt)[33] = (float(*)[33])sbuf;   // [32][33]
    int n0 = (id & 15) * 32, j0 = ((id >> 4) & 15) * 32, b = id >> 8;
    int tx = t & 31, ty = t >> 5;
    #pragma unroll
    for (int r = 0; r < 4; r++) {
        int n = n0 + ty + 8 * r;
        tt[ty + 8 * r][tx] = CI[((size_t)b * NUc + n) * (2 * Lc) + j0 + tx];
    }
    __syncthreads();
    #pragma unroll
    for (int r = 0; r < 4; r++) {
        int j = j0 + ty + 8 * r;
        g_ciT[((size_t)b * 2 * Lc + j) * NUc + n0 + tx] = tt[tx][ty + 8 * r];
    }
}

__device__ void proj_body(float* sbuf, int id, int t,
                          const float* __restrict__ UU, const float* __restrict__ DU,
                          const float* __restrict__ TA,
                          const float* __restrict__ uu_iw, const float* __restrict__ uu_ib,
                          const float* __restrict__ ta_iw, const float* __restrict__ ta_ib,
                          const float* __restrict__ du_iw, const float* __restrict__ du_ib)
{
    int bx = id & 1, by = (id >> 1) & 31, bz = id >> 6;
    const float *X, *W, *bias;
    float* out;
    int K = Ec, sx = Ec, M = Bc * Lc, R = 0;
    switch (bz) {
        case 0: X = DU; W = uu_iw;               bias = uu_ib;           out = g_q_uu;  break;
        case 1: X = DU; W = ta_iw;               bias = ta_ib;           out = g_q_ta;  break;
        case 2: X = DU; W = du_iw;               bias = du_ib;           out = g_q_du;  break;
        case 3: X = TA; W = ta_iw + Ec * Ec;     bias = ta_ib + Ec;      out = g_k_ta;  R = NTc; break;
        case 4: X = TA; W = ta_iw + 2 * Ec * Ec; bias = ta_ib + 2 * Ec;  out = g_v_ta;  R = NTc; break;
        case 5: X = DU; W = du_iw + Ec * Ec;     bias = du_ib + Ec;      out = g_k_du;  R = Lc;  break;
        case 6: X = DU; W = du_iw + 2 * Ec * Ec; bias = du_ib + 2 * Ec;  out = g_v_du;  R = Lc;  break;
        case 7: X = UU; W = uu_iw + Ec * Ec;     bias = uu_ib + Ec;      out = g_kb_uu;
                K = Ec - 2; sx = Ec - 2; M = Bc * NUc; R = NUc; break;
        default: X = UU; W = uu_iw + 2 * Ec * Ec; bias = uu_ib + 2 * Ec; out = g_vb_uu;
                K = Ec - 2; sx = Ec - 2; M = Bc * NUc; R = NUc; break;
    }
    int m0 = by * 64;
    if (m0 >= M) return;
    int n0 = bx * 64;
    int tx = t & 15, ty = t >> 4;
    int lrow = t >> 5, lcol = t & 31;

    float (*Xs)[33] = (float(*)[33])sbuf;          // [64][33]
    float (*Ws)[33] = (float(*)[33])(sbuf + 64*33);
    float acc[4][4];
    #pragma unroll
    for (int i = 0; i < 4; i++)
        #pragma unroll
        for (int j = 0; j < 4; j++) acc[i][j] = 0.f;

    for (int k0 = 0; k0 < K; k0 += 32) {
        int k = k0 + lcol;
        bool kin = (k < K);
        #pragma unroll
        for (int i = 0; i < 8; i++) {
            int row = lrow + 8 * i;
            Xs[row][lcol] = kin ? X[(size_t)(m0 + row) * sx + k] : 0.f;
            Ws[row][lcol] = kin ? W[(size_t)(n0 + row) * Ec + k] : 0.f;
        }
        __syncthreads();
        #pragma unroll
        for (int kk = 0; kk < 32; kk++) {
            float a[4], w[4];
            #pragma unroll
            for (int i = 0; i < 4; i++) a[i] = Xs[ty + 16 * i][kk];
            #pragma unroll
            for (int j = 0; j < 4; j++) w[j] = Ws[tx + 16 * j][kk];
            #pragma unroll
            for (int i = 0; i < 4; i++)
                #pragma unroll
                for (int j = 0; j < 4; j++) acc[i][j] += a[i] * w[j];
        }
        __syncthreads();
    }
    #pragma unroll
    for (int j = 0; j < 4; j++) {
        int n = n0 + tx + 16 * j;
        float bv = bias[n];
        #pragma unroll
        for (int i = 0; i < 4; i++) {
            int m = m0 + ty + 16 * i;
            float v = acc[i][j] + bv;
            if (R == 0) {
                out[(size_t)m * Ec + n] = v;
            } else {
                int bb = m / R, row = m % R;
                out[(((size_t)bb * Hc + (n >> 4)) * R + row) * Dh + (n & 15)] = v;
            }
        }
    }
}

__global__ void __launch_bounds__(256) prep_fused(
    const float* __restrict__ UU, const float* __restrict__ DU,
    const float* __restrict__ TA, const float* __restrict__ CI,
    const float* __restrict__ uu_iw, const float* __restrict__ uu_ib,
    const float* __restrict__ ta_iw, const float* __restrict__ ta_ib,
    const float* __restrict__ du_iw, const float* __restrict__ du_ib,
    const float* __restrict__ dim_w, const float* __restrict__ dim_b,
    const float* __restrict__ uu_ow, const float* __restrict__ uu_ob,
    const float* __restrict__ ta_ow, const float* __restrict__ ta_ob,
    const float* __restrict__ du_ow, const float* __restrict__ du_ob)
{
    __shared__ float sbuf[2 * 64 * 33];
    int id = blockIdx.x;
    int t = threadIdx.x;
    if (id < 48) {
        combine_w_body(sbuf, id, t, dim_w, uu_ow, ta_ow, du_ow);
    } else if (id == 48) {
        if (t < 128) combine_b_body(t, dim_w, dim_b, uu_ob, ta_ob, du_ob);
    } else if (id < 49 + 1024) {
        ci_body(sbuf, id - 49, t, CI);
    } else {
        proj_body(sbuf, id - 1073, t, UU, DU, TA,
                  uu_iw, uu_ib, ta_iw, ta_ib, du_iw, du_ib);
    }
}

// =================== stage 2: fused attention ===================
__device__ __forceinline__ float wred_sum(float v) {
    #pragma unroll
    for (int o = 16; o >= 1; o >>= 1) v += __shfl_xor_sync(0xffffffffu, v, o);
    return v;
}
__device__ __forceinline__ float wred_max(float v) {
    #pragma unroll
    for (int o = 16; o >= 1; o >>= 1) v = fmaxf(v, __shfl_xor_sync(0xffffffffu, v, o));
    return v;
}

template<int NK, bool IS_UU>
__device__ void attn_body(int id, const float* __restrict__ inw, float4* sm4)
{
    constexpr int NPL = NK / 32;
    int lt = id & 15, h = (id >> 4) & 7, z = id >> 7;

    const float *Q, *Kb, *Vb;
    float* O;
    int b;
    if constexpr (IS_UU) {
        b = z;
        Q = g_q_uu; Kb = g_kb_uu; Vb = g_vb_uu; O = g_o_uu;
    } else {
        if (z < Bc) { b = z;      Q = g_q_ta; Kb = g_k_ta; Vb = g_v_ta; O = g_o_ta; }
        else        { b = z - Bc; Q = g_q_du; Kb = g_k_du; Vb = g_v_du; O = g_o_du; }
    }
    int tid = threadIdx.x, warp = tid >> 5, lane = tid & 31;

    const float4* ksrc = (const float4*)(Kb + ((size_t)(b * Hc + h) * NK) * Dh);
    const float4* vsrc = (const float4*)(Vb + ((size_t)(b * Hc + h) * NK) * Dh);

    for (int i = tid; i < NK * 4; i += 128) sm4[(i >> 2) * 5 + (i & 3)] = ksrc[i];
    __syncthreads();

    int l0 = lt * 16 + warp * 4;
    int bl0 = b * Lc + l0;

    float q[4][16];
    #pragma unroll
    for (int qi = 0; qi < 4; qi++) {
        const float4* qp = (const float4*)(Q + (size_t)(bl0 + qi) * Ec + h * Dh);
        #pragma unroll
        for (int j = 0; j < 4; j++) {
            float4 tv = qp[j];
            q[qi][j*4+0] = tv.x; q[qi][j*4+1] = tv.y; q[qi][j*4+2] = tv.z; q[qi][j*4+3] = tv.w;
        }
    }

    float c1k[4], c2k[4];
    const float *cp1[4], *cp2[4];
    if constexpr (IS_UU) {
        #pragma unroll
        for (int qi = 0; qi < 4; qi++) { c1k[qi] = 0.f; c2k[qi] = 0.f; }
        #pragma unroll
        for (int d = 0; d < 16; d++) {
            size_t kr = (size_t)(Ec + h * Dh + d) * Ec;
            float w1 = __ldg(inw + kr + 126), w2 = __ldg(inw + kr + 127);
            #pragma unroll
            for (int qi = 0; qi < 4; qi++) { c1k[qi] += q[qi][d] * w1; c2k[qi] += q[qi][d] * w2; }
        }
        #pragma unroll
        for (int qi = 0; qi < 4; qi++) {
            cp1[qi] = g_ciT + ((size_t)b * 2 * Lc + (l0 + qi)) * NUc;
            cp2[qi] = cp1[qi] + (size_t)Lc * NUc;
        }
    }

    float sv[4][NPL];
    float mx[4] = {-1e30f, -1e30f, -1e30f, -1e30f};
    #pragma unroll
    for (int i = 0; i < NPL; i++) {
        int n = i * 32 + lane;
        const float4* kr = sm4 + n * 5;
        float4 k0 = kr[0], k1 = kr[1], k2 = kr[2], k3 = kr[3];
        #pragma unroll
        for (int qi = 0; qi < 4; qi++) {
            float s = q[qi][0]*k0.x + q[qi][1]*k0.y + q[qi][2]*k0.z + q[qi][3]*k0.w
                    + q[qi][4]*k1.x + q[qi][5]*k1.y + q[qi][6]*k1.z + q[qi][7]*k1.w
                    + q[qi][8]*k2.x + q[qi][9]*k2.y + q[qi][10]*k2.z + q[qi][11]*k2.w
                    + q[qi][12]*k3.x + q[qi][13]*k3.y + q[qi][14]*k3.z + q[qi][15]*k3.w;
            if constexpr (IS_UU) s += cp1[qi][n] * c1k[qi] + cp2[qi][n] * c2k[qi];
            s *= 0.25f;
            sv[qi][i] = s;
            mx[qi] = fmaxf(mx[qi], s);
        }
    }
    float invsum[4];
    #pragma unroll
    for (int qi = 0; qi < 4; qi++) {
        float m = wred_max(mx[qi]);
        float sum = 0.f;
        #pragma unroll
        for (int i = 0; i < NPL; i++) { sv[qi][i] = __expf(sv[qi][i] - m); sum += sv[qi][i]; }
        invsum[qi] = 1.f / wred_sum(sum);
    }

    __syncthreads();
    for (int i = tid; i < NK * 4; i += 128) sm4[(i >> 2) * 5 + (i & 3)] = vsrc[i];
    __syncthreads();

    float a[4][16];
    #pragma unroll
    for (int qi = 0; qi < 4; qi++)
        #pragma unroll
        for (int d = 0; d < 16; d++) a[qi][d] = 0.f;
    float A1[4] = {0.f,0.f,0.f,0.f}, A2[4] = {0.f,0.f,0.f,0.f};
    #pragma unroll
    for (int i = 0; i < NPL; i++) {
        int n = i * 32 + lane;
        const float4* vr = sm4 + n * 5;
        float4 v0 = vr[0], v1 = vr[1], v2 = vr[2], v3 = vr[3];
        #pragma unroll
        for (int qi = 0; qi < 4; qi++) {
            float p = sv[qi][i];
            a[qi][0] += p*v0.x;  a[qi][1] += p*v0.y;  a[qi][2] += p*v0.z;  a[qi][3] += p*v0.w;
            a[qi][4] += p*v1.x;  a[qi][5] += p*v1.y;  a[qi][6] += p*v1.z;  a[qi][7] += p*v1.w;
            a[qi][8] += p*v2.x;  a[qi][9] += p*v2.y;  a[qi][10]+= p*v2.z;  a[qi][11]+= p*v2.w;
            a[qi][12]+= p*v3.x;  a[qi][13]+= p*v3.y;  a[qi][14]+= p*v3.z;  a[qi][15]+= p*v3.w;
            if constexpr (IS_UU) { A1[qi] += p * cp1[qi][n]; A2[qi] += p * cp2[qi][n]; }
        }
    }
    #pragma unroll
    for (int qi = 0; qi < 4; qi++) {
        #pragma unroll
        for (int d = 0; d < 16; d++) a[qi][d] = wred_sum(a[qi][d]);
        if constexpr (IS_UU) { A1[qi] = wred_sum(A1[qi]); A2[qi] = wred_sum(A2[qi]); }
        if (lane == 0) {
            float inv = invsum[qi];
            float o16[16];
            #pragma unroll
            for (int d = 0; d < 16; d++) {
                float v = a[qi][d];
                if constexpr (IS_UU) {
                    size_t vr = (size_t)(2 * Ec + h * Dh + d) * Ec;
                    v += A1[qi] * __ldg(inw + vr + 126) + A2[qi] * __ldg(inw + vr + 127);
                }
                o16[d] = v * inv;
            }
            float4* op = (float4*)(O + (size_t)(bl0 + qi) * Ec + h * Dh);
            op[0] = make_float4(o16[0], o16[1], o16[2], o16[3]);
            op[1] = make_float4(o16[4], o16[5], o16[6], o16[7]);
            op[2] = make_float4(o16[8], o16[9], o16[10], o16[11]);
            op[3] = make_float4(o16[12], o16[13], o16[14], o16[15]);
        }
    }
}

__global__ void __launch_bounds__(128, 3) attn_fused(const float* __restrict__ inw)
{
    extern __shared__ float4 sm4[];
    int id = blockIdx.x;
    if (id < 512) attn_body<NUc, true>(id, inw, sm4);
    else          attn_body<NTc, false>(id - 512, nullptr, sm4);
}

// =================== stage 3: final GEMM + BN partials ===================
__global__ void __launch_bounds__(256) final_gemm()
{
    int m0 = blockIdx.y * 64, n0 = blockIdx.x * 64;
    int t = threadIdx.x;
    int tx = t & 15, ty = t >> 4;
    int lrow = t >> 5, lcol = t & 31;

    __shared__ float Xs[64][33];
    __shared__ float Ws[64][33];
    __shared__ float shs[16][64], shs2[16][64];
    float acc[4][4];
    #pragma unroll
    for (int i = 0; i < 4; i++)
        #pragma unroll
        for (int j = 0; j < 4; j++) acc[i][j] = 0.f;

    for (int k0 = 0; k0 < 3 * Ec; k0 += 32) {
        int seg = k0 >> 7, kl0 = k0 & 127;
        const float* X = (seg == 0) ? g_o_uu : (seg == 1) ? g_o_ta : g_o_du;
        const float* W = g_WR[seg];
        #pragma unroll
        for (int i = 0; i < 8; i++) {
            int row = lrow + 8 * i;
            Xs[row][lcol] = X[(size_t)(m0 + row) * Ec + kl0 + lcol];
            Ws[row][lcol] = W[(size_t)(n0 + row) * Ec + kl0 + lcol];
        }
        __syncthreads();
        #pragma unroll
        for (int kk = 0; kk < 32; kk++) {
            float a[4], w[4];
            #pragma unroll
            for (int i = 0; i < 4; i++) a[i] = Xs[ty + 16 * i][kk];
            #pragma unroll
            for (int j = 0; j < 4; j++) w[j] = Ws[tx + 16 * j][kk];
            #pragma unroll
            for (int i = 0; i < 4; i++)
                #pragma unroll
                for (int j = 0; j < 4; j++) acc[i][j] += a[i] * w[j];
        }
        __syncthreads();
    }
    #pragma unroll
    for (int j = 0; j < 4; j++) {
        int n = n0 + tx + 16 * j;
        float bv = g_bcomb[n];
        float ls = 0.f, ls2 = 0.f;
        #pragma unroll
        for (int i = 0; i < 4; i++) {
            int m = m0 + ty + 16 * i;
            float v = acc[i][j] + bv;
            g_y[(size_t)m * Ec + n] = v;
            ls += v; ls2 += v * v;
        }
        shs[ty][tx + 16 * j] = ls;
        shs2[ty][tx + 16 * j] = ls2;
    }
    __syncthreads();
    #pragma unroll
    for (int off = 8; off >= 1; off >>= 1) {
        if (ty < off) {
            #pragma unroll
            for (int j = 0; j < 4; j++) {
                int c = tx + 16 * j;
                shs[ty][c] += shs[ty + off][c];
                shs2[ty][c] += shs2[ty + off][c];
            }
        }
        __syncthreads();
    }
    if (ty == 0) {
        #pragma unroll
        for (int j = 0; j < 4; j++) {
            int c = tx + 16 * j;
            g_part[blockIdx.y][0][n0 + c] = shs[0][c];
            g_part[blockIdx.y][1][n0 + c] = shs2[0][c];
        }
    }
}

// =================== stage 4: BN finalize + apply + relu ===================
__global__ void __launch_bounds__(512) bn_apply2(const float* __restrict__ gamma,
                                                 const float* __restrict__ beta,
                                                 float* __restrict__ out)
{
    __shared__ float smean[Ec], srstd[Ec];
    int t = threadIdx.x;
    if (t < Ec) {
        float S = 0.f, S2 = 0.f;
        #pragma unroll
        for (int c = 0; c < 16; c++) { S += g_part[c][0][t]; S2 += g_part[c][1][t]; }
        float mean = S / (Bc * Lc);
        float var = S2 / (Bc * Lc) - mean * mean;
        smean[t] = mean;
        srstd[t] = rsqrtf(var + 1e-5f);
    }
    __syncthreads();
    int i = blockIdx.x * 512 + t;
    int e = i & (Ec - 1);
    float v = (g_y[i] - smean[e]) * srstd[e] * gamma[e] + beta[e];
    out[i] = fmaxf(v, 0.f);
}

extern "C" void kernel_launch(void* const* d_in, const int* in_sizes, int n_in,
                              void* d_out, int out_size)
{
    const float* UUMat   = (const float*)d_in[0];
    const float* DUMat   = (const float*)d_in[1];
    const float* TAMat   = (const float*)d_in[2];
    const float* CIMat   = (const float*)d_in[3];
    const float* uu_in_w = (const float*)d_in[4];
    const float* uu_in_b = (const float*)d_in[5];
    const float* uu_out_w= (const float*)d_in[6];
    const float* uu_out_b= (const float*)d_in[7];
    const float* ta_in_w = (const float*)d_in[8];
    const float* ta_in_b = (const float*)d_in[9];
    const float* ta_out_w= (const float*)d_in[10];
    const float* ta_out_b= (const float*)d_in[11];
    const float* du_in_w = (const float*)d_in[12];
    const float* du_in_b = (const float*)d_in[13];
    const float* du_out_w= (const float*)d_in[14];
    const float* du_out_b= (const float*)d_in[15];
    const float* dim_w   = (const float*)d_in[16];
    const float* dim_b   = (const float*)d_in[17];
    const float* bn_gamma= (const float*)d_in[18];
    const float* bn_beta = (const float*)d_in[19];
    float* out = (float*)d_out;

    prep_fused<<<1649, 256>>>(UUMat, DUMat, TAMat, CIMat,
                              uu_in_w, uu_in_b, ta_in_w, ta_in_b, du_in_w, du_in_b,
                              dim_w, dim_b, uu_out_w, uu_out_b,
                              ta_out_w, ta_out_b, du_out_w, du_out_b);

    attn_fused<<<1536, 128, NUc * 5 * sizeof(float4)>>>(uu_in_w);

    final_gemm<<<dim3(2, 16), 256>>>();

    bn_apply2<<<(Bc * Lc * Ec) / 512, 512>>>(bn_gamma, bn_beta, out);
}

// round 8
// speedup vs baseline: 1.4168x; 1.2487x over previous
#include <cuda_runtime.h>
#include <math.h>

#define Bc 4
#define Lc 256
#define Ec 128
#define Hc 8
#define Dh 16
#define NUc 512
#define NTc 256

#define KST 68   // k-major smem row stride (floats): 272B = 17*16B -> LDS.128-aligned rows

// ---------------- scratch (device globals; no allocation) ----------------
__device__ float g_q_uu[Bc*Lc*Ec];
__device__ float g_q_ta[Bc*Lc*Ec];
__device__ float g_q_du[Bc*Lc*Ec];
__device__ float g_k_ta[Bc*NTc*Ec];   // head-blocked [b][h][n][16]
__device__ float g_v_ta[Bc*NTc*Ec];
__device__ float g_k_du[Bc*Lc*Ec];
__device__ float g_v_du[Bc*Lc*Ec];
__device__ float g_kb_uu[Bc*NUc*Ec];
__device__ float g_vb_uu[Bc*NUc*Ec];
__device__ float g_ciT[Bc*2*Lc*NUc];  // [b][j][n]
__device__ float g_o_uu[Bc*Lc*Ec];
__device__ float g_o_ta[Bc*Lc*Ec];
__device__ float g_o_du[Bc*Lc*Ec];
__device__ float g_WR[3][Ec*Ec];      // combined weights, row-major [seg][e][j]
__device__ float g_bcomb[Ec];
__device__ float g_y[Bc*Lc*Ec];
__device__ float g_part[16][2][Ec];   // per-row-tile channel sums / sumsq

// =================== stage 1: fused prep ===================
// blocks [0,48): combine_w | block 48: combine_b
// blocks [49,1073): ci_transpose | blocks [1073,1649): proj

__device__ void combine_w_body(float* sbuf, int id, int t,
                               const float* __restrict__ dim_w,
                               const float* __restrict__ uu_ow,
                               const float* __restrict__ ta_ow,
                               const float* __restrict__ du_ow)
{
    int bx = id & 3, by = (id >> 2) & 3, m = id >> 4;
    const float* ow = (m == 0) ? uu_ow : (m == 1) ? ta_ow : du_ow;
    float* dst = g_WR[m];
    int j0 = bx * 32, e0 = by * 32;
    int tx = t & 31, ty = t >> 5;
    float (*dws)[33] = (float(*)[33])sbuf;
    float (*ows)[33] = (float(*)[33])(sbuf + 32*33);

    float acc[4] = {0.f, 0.f, 0.f, 0.f};
    for (int k0 = 0; k0 < Ec; k0 += 32) {
        #pragma unroll
        for (int r = 0; r < 4; r++) {
            int row = ty + 8 * r;
            dws[row][tx] = dim_w[(size_t)(e0 + row) * (3 * Ec) + m * Ec + k0 + tx];
            ows[row][tx] = ow[(size_t)(k0 + row) * Ec + j0 + tx];
        }
        __syncthreads();
        #pragma unroll
        for (int kk = 0; kk < 32; kk++) {
            float o = ows[kk][tx];
            #pragma unroll
            for (int r = 0; r < 4; r++) acc[r] += dws[ty + 8 * r][kk] * o;
        }
        __syncthreads();
    }
    #pragma unroll
    for (int r = 0; r < 4; r++)
        dst[(size_t)(e0 + ty + 8 * r) * Ec + j0 + tx] = acc[r];
}

__device__ void combine_b_body(int t,
                               const float* __restrict__ dim_w, const float* __restrict__ dim_b,
                               const float* __restrict__ uu_ob, const float* __restrict__ ta_ob,
                               const float* __restrict__ du_ob)
{
    int warp = t >> 5, lane = t & 31;
    for (int e = warp; e < Ec; e += 4) {
        float s = 0.f;
        #pragma unroll
        for (int i = 0; i < 12; i++) {
            int k = lane + 32 * i;
            const float* ob = (i < 4) ? uu_ob : (i < 8) ? ta_ob : du_ob;
            int kl = k - (i < 4 ? 0 : (i < 8 ? Ec : 2 * Ec));
            s += dim_w[(size_t)e * (3 * Ec) + k] * ob[kl];
        }
        #pragma unroll
        for (int o = 16; o >= 1; o >>= 1) s += __shfl_xor_sync(0xffffffffu, s, o);
        if (lane == 0) g_bcomb[e] = dim_b[e] + s;
    }
}

__device__ void ci_body(float* sbuf, int id, int t, const float* __restrict__ CI)
{
    float (*tt)[33] = (float(*)[33])sbuf;
    int n0 = (id & 15) * 32, j0 = ((id >> 4) & 15) * 32, b = id >> 8;
    int tx = t & 31, ty = t >> 5;
    #pragma unroll
    for (int r = 0; r < 4; r++) {
        int n = n0 + ty + 8 * r;
        tt[ty + 8 * r][tx] = CI[((size_t)b * NUc + n) * (2 * Lc) + j0 + tx];
    }
    __syncthreads();
    #pragma unroll
    for (int r = 0; r < 4; r++) {
        int j = j0 + ty + 8 * r;
        g_ciT[((size_t)b * 2 * Lc + j) * NUc + n0 + tx] = tt[tx][ty + 8 * r];
    }
}

// k-major smem, vectorized LDS GEMM body: 64x64 tile, thread tile 4x4 contiguous
__device__ void proj_body(float* sbuf, int id, int t,
                          const float* __restrict__ UU, const float* __restrict__ DU,
                          const float* __restrict__ TA,
                          const float* __restrict__ uu_iw, const float* __restrict__ uu_ib,
                          const float* __restrict__ ta_iw, const float* __restrict__ ta_ib,
                          const float* __restrict__ du_iw, const float* __restrict__ du_ib)
{
    int bx = id & 1, by = (id >> 1) & 31, bz = id >> 6;
    const float *X, *W, *bias;
    float* out;
    int K = Ec, sx = Ec, M = Bc * Lc, R = 0;
    switch (bz) {
        case 0: X = DU; W = uu_iw;               bias = uu_ib;           out = g_q_uu;  break;
        case 1: X = DU; W = ta_iw;               bias = ta_ib;           out = g_q_ta;  break;
        case 2: X = DU; W = du_iw;               bias = du_ib;           out = g_q_du;  break;
        case 3: X = TA; W = ta_iw + Ec * Ec;     bias = ta_ib + Ec;      out = g_k_ta;  R = NTc; break;
        case 4: X = TA; W = ta_iw + 2 * Ec * Ec; bias = ta_ib + 2 * Ec;  out = g_v_ta;  R = NTc; break;
        case 5: X = DU; W = du_iw + Ec * Ec;     bias = du_ib + Ec;      out = g_k_du;  R = Lc;  break;
        case 6: X = DU; W = du_iw + 2 * Ec * Ec; bias = du_ib + 2 * Ec;  out = g_v_du;  R = Lc;  break;
        case 7: X = UU; W = uu_iw + Ec * Ec;     bias = uu_ib + Ec;      out = g_kb_uu;
                K = Ec - 2; sx = Ec - 2; M = Bc * NUc; R = NUc; break;
        default: X = UU; W = uu_iw + 2 * Ec * Ec; bias = uu_ib + 2 * Ec; out = g_vb_uu;
                K = Ec - 2; sx = Ec - 2; M = Bc * NUc; R = NUc; break;
    }
    int m0 = by * 64;
    if (m0 >= M) return;
    int n0 = bx * 64;
    int tx = t & 15, ty = t >> 4;           // thread tile: rows m0+4ty.., cols n0+4tx..
    int lrow = t >> 5, lcol = t & 31;

    float (*XsT)[KST] = (float(*)[KST])sbuf;            // [k][m]
    float (*WsT)[KST] = (float(*)[KST])(sbuf + 32*KST); // [k][n]
    float acc[4][4];
    #pragma unroll
    for (int i = 0; i < 4; i++)
        #pragma unroll
        for (int j = 0; j < 4; j++) acc[i][j] = 0.f;

    for (int k0 = 0; k0 < K; k0 += 32) {
        int k = k0 + lcol;
        bool kin = (k < K);
        #pragma unroll
        for (int i = 0; i < 8; i++) {
            int row = lrow + 8 * i;
            XsT[lcol][row] = kin ? X[(size_t)(m0 + row) * sx + k] : 0.f;
            WsT[lcol][row] = kin ? W[(size_t)(n0 + row) * Ec + k] : 0.f;
        }
        __syncthreads();
        #pragma unroll
        for (int kk = 0; kk < 32; kk++) {
            float4 av = *(const float4*)&XsT[kk][ty * 4];
            float4 wv = *(const float4*)&WsT[kk][tx * 4];
            float a4[4] = {av.x, av.y, av.z, av.w};
            float w4[4] = {wv.x, wv.y, wv.z, wv.w};
            #pragma unroll
            for (int i = 0; i < 4; i++)
                #pragma unroll
                for (int j = 0; j < 4; j++) acc[i][j] += a4[i] * w4[j];
        }
        __syncthreads();
    }
    int n = n0 + tx * 4;
    float4 bv = *(const float4*)&bias[n];
    float b4[4] = {bv.x, bv.y, bv.z, bv.w};
    #pragma unroll
    for (int i = 0; i < 4; i++) {
        int m = m0 + ty * 4 + i;
        float4 v = make_float4(acc[i][0] + b4[0], acc[i][1] + b4[1],
                               acc[i][2] + b4[2], acc[i][3] + b4[3]);
        if (R == 0) {
            *(float4*)&out[(size_t)m * Ec + n] = v;
        } else {
            int bb = m / R, row = m % R;
            *(float4*)&out[(((size_t)bb * Hc + (n >> 4)) * R + row) * Dh + (n & 15)] = v;
        }
    }
}

__global__ void __launch_bounds__(256) prep_fused(
    const float* __restrict__ UU, const float* __restrict__ DU,
    const float* __restrict__ TA, const float* __restrict__ CI,
    const float* __restrict__ uu_iw, const float* __restrict__ uu_ib,
    const float* __restrict__ ta_iw, const float* __restrict__ ta_ib,
    const float* __restrict__ du_iw, const float* __restrict__ du_ib,
    const float* __restrict__ dim_w, const float* __restrict__ dim_b,
    const float* __restrict__ uu_ow, const float* __restrict__ uu_ob,
    const float* __restrict__ ta_ow, const float* __restrict__ ta_ob,
    const float* __restrict__ du_ow, const float* __restrict__ du_ob)
{
    __shared__ __align__(16) float sbuf[2 * 32 * KST];
    int id = blockIdx.x;
    int t = threadIdx.x;
    if (id < 48) {
        combine_w_body(sbuf, id, t, dim_w, uu_ow, ta_ow, du_ow);
    } else if (id == 48) {
        if (t < 128) combine_b_body(t, dim_w, dim_b, uu_ob, ta_ob, du_ob);
    } else if (id < 49 + 1024) {
        ci_body(sbuf, id - 49, t, CI);
    } else {
        proj_body(sbuf, id - 1073, t, UU, DU, TA,
                  uu_iw, uu_ib, ta_iw, ta_ib, du_iw, du_ib);
    }
}

// =================== stage 2: fused attention ===================
__device__ __forceinline__ float wred_sum(float v) {
    #pragma unroll
    for (int o = 16; o >= 1; o >>= 1) v += __shfl_xor_sync(0xffffffffu, v, o);
    return v;
}
__device__ __forceinline__ float wred_max(float v) {
    #pragma unroll
    for (int o = 16; o >= 1; o >>= 1) v = fmaxf(v, __shfl_xor_sync(0xffffffffu, v, o));
    return v;
}

template<int NK, bool IS_UU>
__device__ void attn_body(int id, const float* __restrict__ inw, float4* sm4)
{
    constexpr int NPL = NK / 32;
    int lt = id & 15, h = (id >> 4) & 7, z = id >> 7;

    const float *Q, *Kb, *Vb;
    float* O;
    int b;
    if constexpr (IS_UU) {
        b = z;
        Q = g_q_uu; Kb = g_kb_uu; Vb = g_vb_uu; O = g_o_uu;
    } else {
        if (z < Bc) { b = z;      Q = g_q_ta; Kb = g_k_ta; Vb = g_v_ta; O = g_o_ta; }
        else        { b = z - Bc; Q = g_q_du; Kb = g_k_du; Vb = g_v_du; O = g_o_du; }
    }
    int tid = threadIdx.x, warp = tid >> 5, lane = tid & 31;

    const float4* ksrc = (const float4*)(Kb + ((size_t)(b * Hc + h) * NK) * Dh);
    const float4* vsrc = (const float4*)(Vb + ((size_t)(b * Hc + h) * NK) * Dh);

    for (int i = tid; i < NK * 4; i += 128) sm4[(i >> 2) * 5 + (i & 3)] = ksrc[i];
    __syncthreads();

    int l0 = lt * 16 + warp * 4;
    int bl0 = b * Lc + l0;

    float q[4][16];
    #pragma unroll
    for (int qi = 0; qi < 4; qi++) {
        const float4* qp = (const float4*)(Q + (size_t)(bl0 + qi) * Ec + h * Dh);
        #pragma unroll
        for (int j = 0; j < 4; j++) {
            float4 tv = qp[j];
            q[qi][j*4+0] = tv.x; q[qi][j*4+1] = tv.y; q[qi][j*4+2] = tv.z; q[qi][j*4+3] = tv.w;
        }
    }

    float c1k[4], c2k[4];
    const float *cp1[4], *cp2[4];
    if constexpr (IS_UU) {
        #pragma unroll
        for (int qi = 0; qi < 4; qi++) { c1k[qi] = 0.f; c2k[qi] = 0.f; }
        #pragma unroll
        for (int d = 0; d < 16; d++) {
            size_t kr = (size_t)(Ec + h * Dh + d) * Ec;
            float w1 = __ldg(inw + kr + 126), w2 = __ldg(inw + kr + 127);
            #pragma unroll
            for (int qi = 0; qi < 4; qi++) { c1k[qi] += q[qi][d] * w1; c2k[qi] += q[qi][d] * w2; }
        }
        #pragma unroll
        for (int qi = 0; qi < 4; qi++) {
            cp1[qi] = g_ciT + ((size_t)b * 2 * Lc + (l0 + qi)) * NUc;
            cp2[qi] = cp1[qi] + (size_t)Lc * NUc;
        }
    }

    float sv[4][NPL];
    float mx[4] = {-1e30f, -1e30f, -1e30f, -1e30f};
    #pragma unroll
    for (int i = 0; i < NPL; i++) {
        int n = i * 32 + lane;
        const float4* kr = sm4 + n * 5;
        float4 k0 = kr[0], k1 = kr[1], k2 = kr[2], k3 = kr[3];
        #pragma unroll
        for (int qi = 0; qi < 4; qi++) {
            float s = q[qi][0]*k0.x + q[qi][1]*k0.y + q[qi][2]*k0.z + q[qi][3]*k0.w
                    + q[qi][4]*k1.x + q[qi][5]*k1.y + q[qi][6]*k1.z + q[qi][7]*k1.w
                    + q[qi][8]*k2.x + q[qi][9]*k2.y + q[qi][10]*k2.z + q[qi][11]*k2.w
                    + q[qi][12]*k3.x + q[qi][13]*k3.y + q[qi][14]*k3.z + q[qi][15]*k3.w;
            if constexpr (IS_UU) s += cp1[qi][n] * c1k[qi] + cp2[qi][n] * c2k[qi];
            s *= 0.25f;
            sv[qi][i] = s;
            mx[qi] = fmaxf(mx[qi], s);
        }
    }
    float invsum[4];
    #pragma unroll
    for (int qi = 0; qi < 4; qi++) {
        float m = wred_max(mx[qi]);
        float sum = 0.f;
        #pragma unroll
        for (int i = 0; i < NPL; i++) { sv[qi][i] = __expf(sv[qi][i] - m); sum += sv[qi][i]; }
        invsum[qi] = 1.f / wred_sum(sum);
    }

    __syncthreads();
    for (int i = tid; i < NK * 4; i += 128) sm4[(i >> 2) * 5 + (i & 3)] = vsrc[i];
    __syncthreads();

    float a[4][16];
    #pragma unroll
    for (int qi = 0; qi < 4; qi++)
        #pragma unroll
        for (int d = 0; d < 16; d++) a[qi][d] = 0.f;
    float A1[4] = {0.f,0.f,0.f,0.f}, A2[4] = {0.f,0.f,0.f,0.f};
    #pragma unroll
    for (int i = 0; i < NPL; i++) {
        int n = i * 32 + lane;
        const float4* vr = sm4 + n * 5;
        float4 v0 = vr[0], v1 = vr[1], v2 = vr[2], v3 = vr[3];
        #pragma unroll
        for (int qi = 0; qi < 4; qi++) {
            float p = sv[qi][i];
            a[qi][0] += p*v0.x;  a[qi][1] += p*v0.y;  a[qi][2] += p*v0.z;  a[qi][3] += p*v0.w;
            a[qi][4] += p*v1.x;  a[qi][5] += p*v1.y;  a[qi][6] += p*v1.z;  a[qi][7] += p*v1.w;
            a[qi][8] += p*v2.x;  a[qi][9] += p*v2.y;  a[qi][10]+= p*v2.z;  a[qi][11]+= p*v2.w;
            a[qi][12]+= p*v3.x;  a[qi][13]+= p*v3.y;  a[qi][14]+= p*v3.z;  a[qi][15]+= p*v3.w;
            if constexpr (IS_UU) { A1[qi] += p * cp1[qi][n]; A2[qi] += p * cp2[qi][n]; }
        }
    }
    #pragma unroll
    for (int qi = 0; qi < 4; qi++) {
        #pragma unroll
        for (int d = 0; d < 16; d++) a[qi][d] = wred_sum(a[qi][d]);
        if constexpr (IS_UU) { A1[qi] = wred_sum(A1[qi]); A2[qi] = wred_sum(A2[qi]); }
        if (lane == 0) {
            float inv = invsum[qi];
            float o16[16];
            #pragma unroll
            for (int d = 0; d < 16; d++) {
                float v = a[qi][d];
                if constexpr (IS_UU) {
                    size_t vr = (size_t)(2 * Ec + h * Dh + d) * Ec;
                    v += A1[qi] * __ldg(inw + vr + 126) + A2[qi] * __ldg(inw + vr + 127);
                }
                o16[d] = v * inv;
            }
            float4* op = (float4*)(O + (size_t)(bl0 + qi) * Ec + h * Dh);
            op[0] = make_float4(o16[0], o16[1], o16[2], o16[3]);
            op[1] = make_float4(o16[4], o16[5], o16[6], o16[7]);
            op[2] = make_float4(o16[8], o16[9], o16[10], o16[11]);
            op[3] = make_float4(o16[12], o16[13], o16[14], o16[15]);
        }
    }
}

__global__ void __launch_bounds__(128, 4) attn_fused(const float* __restrict__ inw)
{
    extern __shared__ float4 sm4[];
    int id = blockIdx.x;
    if (id < 512) attn_body<NUc, true>(id, inw, sm4);
    else          attn_body<NTc, false>(id - 512, nullptr, sm4);
}

// =================== stage 3: final GEMM + BN partials ===================
__global__ void __launch_bounds__(256) final_gemm()
{
    int m0 = blockIdx.y * 64, n0 = blockIdx.x * 64;
    int t = threadIdx.x;
    int tx = t & 15, ty = t >> 4;
    int lrow = t >> 5, lcol = t & 31;

    __shared__ __align__(16) float XsT[32][KST];
    __shared__ __align__(16) float WsT[32][KST];
    __shared__ float shs[16][64], shs2[16][64];
    float acc[4][4];
    #pragma unroll
    for (int i = 0; i < 4; i++)
        #pragma unroll
        for (int j = 0; j < 4; j++) acc[i][j] = 0.f;

    for (int k0 = 0; k0 < 3 * Ec; k0 += 32) {
        int seg = k0 >> 7, kl0 = k0 & 127;
        const float* X = (seg == 0) ? g_o_uu : (seg == 1) ? g_o_ta : g_o_du;
        const float* W = g_WR[seg];
        #pragma unroll
        for (int i = 0; i < 8; i++) {
            int row = lrow + 8 * i;
            XsT[lcol][row] = X[(size_t)(m0 + row) * Ec + kl0 + lcol];
            WsT[lcol][row] = W[(size_t)(n0 + row) * Ec + kl0 + lcol];
        }
        __syncthreads();
        #pragma unroll
        for (int kk = 0; kk < 32; kk++) {
            float4 av = *(const float4*)&XsT[kk][ty * 4];
            float4 wv = *(const float4*)&WsT[kk][tx * 4];
            float a4[4] = {av.x, av.y, av.z, av.w};
            float w4[4] = {wv.x, wv.y, wv.z, wv.w};
            #pragma unroll
            for (int i = 0; i < 4; i++)
                #pragma unroll
                for (int j = 0; j < 4; j++) acc[i][j] += a4[i] * w4[j];
        }
        __syncthreads();
    }
    int n = n0 + tx * 4;
    float4 bv = *(const float4*)&g_bcomb[n];
    float b4[4] = {bv.x, bv.y, bv.z, bv.w};
    float cs[4] = {0.f,0.f,0.f,0.f}, cs2[4] = {0.f,0.f,0.f,0.f};
    #pragma unroll
    for (int i = 0; i < 4; i++) {
        int m = m0 + ty * 4 + i;
        float v0 = acc[i][0] + b4[0], v1 = acc[i][1] + b4[1];
        float v2 = acc[i][2] + b4[2], v3 = acc[i][3] + b4[3];
        *(float4*)&g_y[(size_t)m * Ec + n] = make_float4(v0, v1, v2, v3);
        cs[0] += v0; cs[1] += v1; cs[2] += v2; cs[3] += v3;
        cs2[0] += v0*v0; cs2[1] += v1*v1; cs2[2] += v2*v2; cs2[3] += v3*v3;
    }
    #pragma unroll
    for (int j = 0; j < 4; j++) { shs[ty][tx*4+j] = cs[j]; shs2[ty][tx*4+j] = cs2[j]; }
    __syncthreads();
    #pragma unroll
    for (int off = 8; off >= 1; off >>= 1) {
        if (ty < off) {
            #pragma unroll
            for (int j = 0; j < 4; j++) {
                int c = tx * 4 + j;
                shs[ty][c] += shs[ty + off][c];
                shs2[ty][c] += shs2[ty + off][c];
            }
        }
        __syncthreads();
    }
    if (ty == 0) {
        #pragma unroll
        for (int j = 0; j < 4; j++) {
            int c = tx * 4 + j;
            g_part[blockIdx.y][0][n0 + c] = shs[0][c];
            g_part[blockIdx.y][1][n0 + c] = shs2[0][c];
        }
    }
}

// =================== stage 4: BN finalize + apply + relu (float4) ===================
__global__ void __launch_bounds__(512) bn_apply2(const float* __restrict__ gamma,
                                                 const float* __restrict__ beta,
                                                 float* __restrict__ out)
{
    __shared__ float sscale[Ec], sshift[Ec];
    int t = threadIdx.x;
    if (t < Ec) {
        float S = 0.f, S2 = 0.f;
        #pragma unroll
        for (int c = 0; c < 16; c++) { S += g_part[c][0][t]; S2 += g_part[c][1][t]; }
        float mean = S / (Bc * Lc);
        float var = S2 / (Bc * Lc) - mean * mean;
        float rs = rsqrtf(var + 1e-5f) * gamma[t];
        sscale[t] = rs;
        sshift[t] = beta[t] - mean * rs;
    }
    __syncthreads();
    int i4 = blockIdx.x * 512 + t;                 // float4 index
    int e0 = (i4 & 31) * 4;
    float4 v = ((const float4*)g_y)[i4];
    v.x = fmaxf(v.x * sscale[e0+0] + sshift[e0+0], 0.f);
    v.y = fmaxf(v.y * sscale[e0+1] + sshift[e0+1], 0.f);
    v.z = fmaxf(v.z * sscale[e0+2] + sshift[e0+2], 0.f);
    v.w = fmaxf(v.w * sscale[e0+3] + sshift[e0+3], 0.f);
    ((float4*)out)[i4] = v;
}

extern "C" void kernel_launch(void* const* d_in, const int* in_sizes, int n_in,
                              void* d_out, int out_size)
{
    const float* UUMat   = (const float*)d_in[0];
    const float* DUMat   = (const float*)d_in[1];
    const float* TAMat   = (const float*)d_in[2];
    const float* CIMat   = (const float*)d_in[3];
    const float* uu_in_w = (const float*)d_in[4];
    const float* uu_in_b = (const float*)d_in[5];
    const float* uu_out_w= (const float*)d_in[6];
    const float* uu_out_b= (const float*)d_in[7];
    const float* ta_in_w = (const float*)d_in[8];
    const float* ta_in_b = (const float*)d_in[9];
    const float* ta_out_w= (const float*)d_in[10];
    const float* ta_out_b= (const float*)d_in[11];
    const float* du_in_w = (const float*)d_in[12];
    const float* du_in_b = (const float*)d_in[13];
    const float* du_out_w= (const float*)d_in[14];
    const float* du_out_b= (const float*)d_in[15];
    const float* dim_w   = (const float*)d_in[16];
    const float* dim_b   = (const float*)d_in[17];
    const float* bn_gamma= (const float*)d_in[18];
    const float* bn_beta = (const float*)d_in[19];
    float* out = (float*)d_out;

    prep_fused<<<1649, 256>>>(UUMat, DUMat, TAMat, CIMat,
                              uu_in_w, uu_in_b, ta_in_w, ta_in_b, du_in_w, du_in_b,
                              dim_w, dim_b, uu_out_w, uu_out_b,
                              ta_out_w, ta_out_b, du_out_w, du_out_b);

    attn_fused<<<1536, 128, NUc * 5 * sizeof(float4)>>>(uu_in_w);

    final_gemm<<<dim3(2, 16), 256>>>();

    bn_apply2<<<(Bc * Lc * Ec / 4) / 512, 512>>>(bn_gamma, bn_beta, out);
}

// round 9
// speedup vs baseline: 1.5503x; 1.0943x over previous
#include <cuda_runtime.h>
#include <math.h>

#define Bc 4
#define Lc 256
#define Ec 128
#define Hc 8
#define Dh 16
#define NUc 512
#define NTc 256

#define KST 68   // k-major smem row stride (floats): 272B -> 16B-aligned rows
#define XST 36   // 32-row variant: 144B -> 16B-aligned rows

// ---------------- scratch (device globals; no allocation) ----------------
__device__ float g_q_uu[Bc*Lc*Ec];
__device__ float g_q_ta[Bc*Lc*Ec];
__device__ float g_q_du[Bc*Lc*Ec];
__device__ float g_k_ta[Bc*NTc*Ec];   // head-blocked [b][h][n][16]
__device__ float g_v_ta[Bc*NTc*Ec];
__device__ float g_k_du[Bc*Lc*Ec];
__device__ float g_v_du[Bc*Lc*Ec];
__device__ float g_kb_uu[Bc*NUc*Ec];
__device__ float g_vb_uu[Bc*NUc*Ec];
__device__ float g_ciT[Bc*2*Lc*NUc];  // [b][j][n]
__device__ float g_o_uu[Bc*Lc*Ec];
__device__ float g_o_ta[Bc*Lc*Ec];
__device__ float g_o_du[Bc*Lc*Ec];
__device__ float g_WR[3][Ec*Ec];      // combined weights, row-major [seg][e][j]
__device__ float g_bcomb[Ec];
__device__ float g_part[32][2][Ec];   // per-m-tile channel sums / sumsq
__device__ int   g_cnt = 0;
__device__ int   g_gen = 0;

// =================== stage 1: fused prep ===================
__device__ void combine_w_body(float* sbuf, int id, int t,
                               const float* __restrict__ dim_w,
                               const float* __restrict__ uu_ow,
                               const float* __restrict__ ta_ow,
                               const float* __restrict__ du_ow)
{
    int bx = id & 3, by = (id >> 2) & 3, m = id >> 4;
    const float* ow = (m == 0) ? uu_ow : (m == 1) ? ta_ow : du_ow;
    float* dst = g_WR[m];
    int j0 = bx * 32, e0 = by * 32;
    int tx = t & 31, ty = t >> 5;
    float (*dws)[33] = (float(*)[33])sbuf;
    float (*ows)[33] = (float(*)[33])(sbuf + 32*33);

    float acc[4] = {0.f, 0.f, 0.f, 0.f};
    for (int k0 = 0; k0 < Ec; k0 += 32) {
        #pragma unroll
        for (int r = 0; r < 4; r++) {
            int row = ty + 8 * r;
            dws[row][tx] = dim_w[(size_t)(e0 + row) * (3 * Ec) + m * Ec + k0 + tx];
            ows[row][tx] = ow[(size_t)(k0 + row) * Ec + j0 + tx];
        }
        __syncthreads();
        #pragma unroll
        for (int kk = 0; kk < 32; kk++) {
            float o = ows[kk][tx];
            #pragma unroll
            for (int r = 0; r < 4; r++) acc[r] += dws[ty + 8 * r][kk] * o;
        }
        __syncthreads();
    }
    #pragma unroll
    for (int r = 0; r < 4; r++)
        dst[(size_t)(e0 + ty + 8 * r) * Ec + j0 + tx] = acc[r];
}

__device__ void combine_b_body(int t,
                               const float* __restrict__ dim_w, const float* __restrict__ dim_b,
                               const float* __restrict__ uu_ob, const float* __restrict__ ta_ob,
                               const float* __restrict__ du_ob)
{
    int warp = t >> 5, lane = t & 31;
    for (int e = warp; e < Ec; e += 4) {
        float s = 0.f;
        #pragma unroll
        for (int i = 0; i < 12; i++) {
            int k = lane + 32 * i;
            const float* ob = (i < 4) ? uu_ob : (i < 8) ? ta_ob : du_ob;
            int kl = k - (i < 4 ? 0 : (i < 8 ? Ec : 2 * Ec));
            s += dim_w[(size_t)e * (3 * Ec) + k] * ob[kl];
        }
        #pragma unroll
        for (int o = 16; o >= 1; o >>= 1) s += __shfl_xor_sync(0xffffffffu, s, o);
        if (lane == 0) g_bcomb[e] = dim_b[e] + s;
    }
}

__device__ void ci_body(float* sbuf, int id, int t, const float* __restrict__ CI)
{
    float (*tt)[33] = (float(*)[33])sbuf;
    int n0 = (id & 15) * 32, j0 = ((id >> 4) & 15) * 32, b = id >> 8;
    int tx = t & 31, ty = t >> 5;
    #pragma unroll
    for (int r = 0; r < 4; r++) {
        int n = n0 + ty + 8 * r;
        tt[ty + 8 * r][tx] = CI[((size_t)b * NUc + n) * (2 * Lc) + j0 + tx];
    }
    __syncthreads();
    #pragma unroll
    for (int r = 0; r < 4; r++) {
        int j = j0 + ty + 8 * r;
        g_ciT[((size_t)b * 2 * Lc + j) * NUc + n0 + tx] = tt[tx][ty + 8 * r];
    }
}

__device__ void proj_body(float* sbuf, int id, int t,
                          const float* __restrict__ UU, const float* __restrict__ DU,
                          const float* __restrict__ TA,
                          const float* __restrict__ uu_iw, const float* __restrict__ uu_ib,
                          const float* __restrict__ ta_iw, const float* __restrict__ ta_ib,
                          const float* __restrict__ du_iw, const float* __restrict__ du_ib)
{
    int bx = id & 1, by = (id >> 1) & 31, bz = id >> 6;
    const float *X, *W, *bias;
    float* out;
    int K = Ec, sx = Ec, M = Bc * Lc, R = 0;
    switch (bz) {
        case 0: X = DU; W = uu_iw;               bias = uu_ib;           out = g_q_uu;  break;
        case 1: X = DU; W = ta_iw;               bias = ta_ib;           out = g_q_ta;  break;
        case 2: X = DU; W = du_iw;               bias = du_ib;           out = g_q_du;  break;
        case 3: X = TA; W = ta_iw + Ec * Ec;     bias = ta_ib + Ec;      out = g_k_ta;  R = NTc; break;
        case 4: X = TA; W = ta_iw + 2 * Ec * Ec; bias = ta_ib + 2 * Ec;  out = g_v_ta;  R = NTc; break;
        case 5: X = DU; W = du_iw + Ec * Ec;     bias = du_ib + Ec;      out = g_k_du;  R = Lc;  break;
        case 6: X = DU; W = du_iw + 2 * Ec * Ec; bias = du_ib + 2 * Ec;  out = g_v_du;  R = Lc;  break;
        case 7: X = UU; W = uu_iw + Ec * Ec;     bias = uu_ib + Ec;      out = g_kb_uu;
                K = Ec - 2; sx = Ec - 2; M = Bc * NUc; R = NUc; break;
        default: X = UU; W = uu_iw + 2 * Ec * Ec; bias = uu_ib + 2 * Ec; out = g_vb_uu;
                K = Ec - 2; sx = Ec - 2; M = Bc * NUc; R = NUc; break;
    }
    int m0 = by * 64;
    if (m0 >= M) return;
    int n0 = bx * 64;
    int tx = t & 15, ty = t >> 4;
    int lrow = t >> 5, lcol = t & 31;

    float (*XsT)[KST] = (float(*)[KST])sbuf;
    float (*WsT)[KST] = (float(*)[KST])(sbuf + 32*KST);
    float acc[4][4];
    #pragma unroll
    for (int i = 0; i < 4; i++)
        #pragma unroll
        for (int j = 0; j < 4; j++) acc[i][j] = 0.f;

    for (int k0 = 0; k0 < K; k0 += 32) {
        int k = k0 + lcol;
        bool kin = (k < K);
        #pragma unroll
        for (int i = 0; i < 8; i++) {
            int row = lrow + 8 * i;
            XsT[lcol][row] = kin ? X[(size_t)(m0 + row) * sx + k] : 0.f;
            WsT[lcol][row] = kin ? W[(size_t)(n0 + row) * Ec + k] : 0.f;
        }
        __syncthreads();
        #pragma unroll
        for (int kk = 0; kk < 32; kk++) {
            float4 av = *(const float4*)&XsT[kk][ty * 4];
            float4 wv = *(const float4*)&WsT[kk][tx * 4];
            float a4[4] = {av.x, av.y, av.z, av.w};
            float w4[4] = {wv.x, wv.y, wv.z, wv.w};
            #pragma unroll
            for (int i = 0; i < 4; i++)
                #pragma unroll
                for (int j = 0; j < 4; j++) acc[i][j] += a4[i] * w4[j];
        }
        __syncthreads();
    }
    int n = n0 + tx * 4;
    float4 bv = *(const float4*)&bias[n];
    float b4[4] = {bv.x, bv.y, bv.z, bv.w};
    #pragma unroll
    for (int i = 0; i < 4; i++) {
        int m = m0 + ty * 4 + i;
        float4 v = make_float4(acc[i][0] + b4[0], acc[i][1] + b4[1],
                               acc[i][2] + b4[2], acc[i][3] + b4[3]);
        if (R == 0) {
            *(float4*)&out[(size_t)m * Ec + n] = v;
        } else {
            int bb = m / R, row = m % R;
            *(float4*)&out[(((size_t)bb * Hc + (n >> 4)) * R + row) * Dh + (n & 15)] = v;
        }
    }
}

__global__ void __launch_bounds__(256) prep_fused(
    const float* __restrict__ UU, const float* __restrict__ DU,
    const float* __restrict__ TA, const float* __restrict__ CI,
    const float* __restrict__ uu_iw, const float* __restrict__ uu_ib,
    const float* __restrict__ ta_iw, const float* __restrict__ ta_ib,
    const float* __restrict__ du_iw, const float* __restrict__ du_ib,
    const float* __restrict__ dim_w, const float* __restrict__ dim_b,
    const float* __restrict__ uu_ow, const float* __restrict__ uu_ob,
    const float* __restrict__ ta_ow, const float* __restrict__ ta_ob,
    const float* __restrict__ du_ow, const float* __restrict__ du_ob)
{
    __shared__ __align__(16) float sbuf[2 * 32 * KST];
    int id = blockIdx.x;
    int t = threadIdx.x;
    if (id < 48) {
        combine_w_body(sbuf, id, t, dim_w, uu_ow, ta_ow, du_ow);
    } else if (id == 48) {
        if (t < 128) combine_b_body(t, dim_w, dim_b, uu_ob, ta_ob, du_ob);
    } else if (id < 49 + 1024) {
        ci_body(sbuf, id - 49, t, CI);
    } else {
        proj_body(sbuf, id - 1073, t, UU, DU, TA,
                  uu_iw, uu_ib, ta_iw, ta_ib, du_iw, du_ib);
    }
}

// =================== stage 2: fused attention ===================
__device__ __forceinline__ float wred_sum(float v) {
    #pragma unroll
    for (int o = 16; o >= 1; o >>= 1) v += __shfl_xor_sync(0xffffffffu, v, o);
    return v;
}
__device__ __forceinline__ float wred_max(float v) {
    #pragma unroll
    for (int o = 16; o >= 1; o >>= 1) v = fmaxf(v, __shfl_xor_sync(0xffffffffu, v, o));
    return v;
}

// one butterfly reduce-scatter stage: vector length 2C -> C, exchange across xor-mask M
template<int M, int C>
__device__ __forceinline__ void bstage(float* red, int lane) {
    bool hi = (lane & M) != 0;
    #pragma unroll
    for (int j = 0; j < C; j++) {
        float send = hi ? red[j] : red[j + C];
        float recv = __shfl_xor_sync(0xffffffffu, send, M);
        red[j] = (hi ? red[j + C] : red[j]) + recv;
    }
}

template<int NK, bool IS_UU>
__device__ void attn_body(int id, const float* __restrict__ inw, float4* sm4)
{
    constexpr int NPL = NK / 32;
    int lt = id & 15, h = (id >> 4) & 7, z = id >> 7;

    const float *Q, *Kb, *Vb;
    float* O;
    int b;
    if constexpr (IS_UU) {
        b = z;
        Q = g_q_uu; Kb = g_kb_uu; Vb = g_vb_uu; O = g_o_uu;
    } else {
        if (z < Bc) { b = z;      Q = g_q_ta; Kb = g_k_ta; Vb = g_v_ta; O = g_o_ta; }
        else        { b = z - Bc; Q = g_q_du; Kb = g_k_du; Vb = g_v_du; O = g_o_du; }
    }
    int tid = threadIdx.x, warp = tid >> 5, lane = tid & 31;

    const float4* ksrc = (const float4*)(Kb + ((size_t)(b * Hc + h) * NK) * Dh);
    const float4* vsrc = (const float4*)(Vb + ((size_t)(b * Hc + h) * NK) * Dh);

    for (int i = tid; i < NK * 4; i += 128) sm4[(i >> 2) * 5 + (i & 3)] = ksrc[i];
    __syncthreads();

    int l0 = lt * 16 + warp * 4;
    int bl0 = b * Lc + l0;

    float q[4][16];
    #pragma unroll
    for (int qi = 0; qi < 4; qi++) {
        const float4* qp = (const float4*)(Q + (size_t)(bl0 + qi) * Ec + h * Dh);
        #pragma unroll
        for (int j = 0; j < 4; j++) {
            float4 tv = qp[j];
            q[qi][j*4+0] = tv.x; q[qi][j*4+1] = tv.y; q[qi][j*4+2] = tv.z; q[qi][j*4+3] = tv.w;
        }
    }

    float c1k[4], c2k[4];
    const float *cp1[4], *cp2[4];
    if constexpr (IS_UU) {
        #pragma unroll
        for (int qi = 0; qi < 4; qi++) { c1k[qi] = 0.f; c2k[qi] = 0.f; }
        #pragma unroll
        for (int d = 0; d < 16; d++) {
            size_t kr = (size_t)(Ec + h * Dh + d) * Ec;
            float w1 = __ldg(inw + kr + 126), w2 = __ldg(inw + kr + 127);
            #pragma unroll
            for (int qi = 0; qi < 4; qi++) { c1k[qi] += q[qi][d] * w1; c2k[qi] += q[qi][d] * w2; }
        }
        #pragma unroll
        for (int qi = 0; qi < 4; qi++) {
            cp1[qi] = g_ciT + ((size_t)b * 2 * Lc + (l0 + qi)) * NUc;
            cp2[qi] = cp1[qi] + (size_t)Lc * NUc;
        }
    }

    float sv[4][NPL];
    float mx[4] = {-1e30f, -1e30f, -1e30f, -1e30f};
    #pragma unroll
    for (int i = 0; i < NPL; i++) {
        int n = i * 32 + lane;
        const float4* kr = sm4 + n * 5;
        float4 k0 = kr[0], k1 = kr[1], k2 = kr[2], k3 = kr[3];
        #pragma unroll
        for (int qi = 0; qi < 4; qi++) {
            float s = q[qi][0]*k0.x + q[qi][1]*k0.y + q[qi][2]*k0.z + q[qi][3]*k0.w
                    + q[qi][4]*k1.x + q[qi][5]*k1.y + q[qi][6]*k1.z + q[qi][7]*k1.w
                    + q[qi][8]*k2.x + q[qi][9]*k2.y + q[qi][10]*k2.z + q[qi][11]*k2.w
                    + q[qi][12]*k3.x + q[qi][13]*k3.y + q[qi][14]*k3.z + q[qi][15]*k3.w;
            if constexpr (IS_UU) s += cp1[qi][n] * c1k[qi] + cp2[qi][n] * c2k[qi];
            s *= 0.25f;
            sv[qi][i] = s;
            mx[qi] = fmaxf(mx[qi], s);
        }
    }
    float invsum[4];
    #pragma unroll
    for (int qi = 0; qi < 4; qi++) {
        float m = wred_max(mx[qi]);
        float sum = 0.f;
        #pragma unroll
        for (int i = 0; i < NPL; i++) { sv[qi][i] = __expf(sv[qi][i] - m); sum += sv[qi][i]; }
        invsum[qi] = 1.f / wred_sum(sum);
    }

    __syncthreads();
    for (int i = tid; i < NK * 4; i += 128) sm4[(i >> 2) * 5 + (i & 3)] = vsrc[i];
    __syncthreads();

    float a[4][16];
    #pragma unroll
    for (int qi = 0; qi < 4; qi++)
        #pragma unroll
        for (int d = 0; d < 16; d++) a[qi][d] = 0.f;
    float A1[4] = {0.f,0.f,0.f,0.f}, A2[4] = {0.f,0.f,0.f,0.f};
    #pragma unroll
    for (int i = 0; i < NPL; i++) {
        int n = i * 32 + lane;
        const float4* vr = sm4 + n * 5;
        float4 v0 = vr[0], v1 = vr[1], v2 = vr[2], v3 = vr[3];
        #pragma unroll
        for (int qi = 0; qi < 4; qi++) {
            float p = sv[qi][i];
            a[qi][0] += p*v0.x;  a[qi][1] += p*v0.y;  a[qi][2] += p*v0.z;  a[qi][3] += p*v0.w;
            a[qi][4] += p*v1.x;  a[qi][5] += p*v1.y;  a[qi][6] += p*v1.z;  a[qi][7] += p*v1.w;
            a[qi][8] += p*v2.x;  a[qi][9] += p*v2.y;  a[qi][10]+= p*v2.z;  a[qi][11]+= p*v2.w;
            a[qi][12]+= p*v3.x;  a[qi][13]+= p*v3.y;  a[qi][14]+= p*v3.z;  a[qi][15]+= p*v3.w;
            if constexpr (IS_UU) { A1[qi] += p * cp1[qi][n]; A2[qi] += p * cp2[qi][n]; }
        }
    }

    // butterfly reduce-scatter epilogue: lane 2d ends with o[d]
    int dL = lane >> 1;
    float wv1L = 0.f, wv2L = 0.f;
    if constexpr (IS_UU) {
        size_t vr = (size_t)(2 * Ec + h * Dh + dL) * Ec;
        wv1L = __ldg(inw + vr + 126);
        wv2L = __ldg(inw + vr + 127);
        #pragma unroll
        for (int qi = 0; qi < 4; qi++) { A1[qi] = wred_sum(A1[qi]); A2[qi] = wred_sum(A2[qi]); }
    }
    #pragma unroll
    for (int qi = 0; qi < 4; qi++) {
        float red[16];
        #pragma unroll
        for (int d = 0; d < 16; d++) red[d] = a[qi][d];
        bstage<16, 8>(red, lane);
        bstage<8, 4>(red, lane);
        bstage<4, 2>(red, lane);
        bstage<2, 1>(red, lane);
        red[0] += __shfl_xor_sync(0xffffffffu, red[0], 1);
        float v = red[0];
        if constexpr (IS_UU) v += A1[qi] * wv1L + A2[qi] * wv2L;
        v *= invsum[qi];
        if (!(lane & 1)) O[(size_t)(bl0 + qi) * Ec + h * Dh + dL] = v;
    }
}

__global__ void __launch_bounds__(128, 4) attn_fused(const float* __restrict__ inw)
{
    extern __shared__ float4 sm4[];
    int id = blockIdx.x;
    if (id < 512) attn_body<NUc, true>(id, inw, sm4);
    else          attn_body<NTc, false>(id - 512, nullptr, sm4);
}

// =================== stage 3: final GEMM + grid-barrier + BN + ReLU ===================
// grid (2, 32): 64 CTAs (single wave), tile 32 rows x 64 cols, y kept in registers
__global__ void __launch_bounds__(256) final_bn(const float* __restrict__ gamma,
                                                const float* __restrict__ beta,
                                                float* __restrict__ out)
{
    int m0 = blockIdx.y * 32, n0 = blockIdx.x * 64;
    int t = threadIdx.x;
    int tx = t & 15, ty = t >> 4;
    int lrow = t >> 5, lcol = t & 31;

    __shared__ __align__(16) float XsT[32][XST];   // [k][m] 32 rows
    __shared__ __align__(16) float WsT[32][KST];   // [k][n] 64 rows
    __shared__ float shs[16][64], shs2[16][64];
    __shared__ float sscale[Ec], sshift[Ec];

    float acc[2][4];
    #pragma unroll
    for (int i = 0; i < 2; i++)
        #pragma unroll
        for (int j = 0; j < 4; j++) acc[i][j] = 0.f;

    for (int k0 = 0; k0 < 3 * Ec; k0 += 32) {
        int seg = k0 >> 7, kl0 = k0 & 127;
        const float* X = (seg == 0) ? g_o_uu : (seg == 1) ? g_o_ta : g_o_du;
        const float* W = g_WR[seg];
        #pragma unroll
        for (int i = 0; i < 4; i++) {
            int row = lrow + 8 * i;
            XsT[lcol][row] = X[(size_t)(m0 + row) * Ec + kl0 + lcol];
        }
        #pragma unroll
        for (int i = 0; i < 8; i++) {
            int row = lrow + 8 * i;
            WsT[lcol][row] = W[(size_t)(n0 + row) * Ec + kl0 + lcol];
        }
        __syncthreads();
        #pragma unroll
        for (int kk = 0; kk < 32; kk++) {
            float2 av = *(const float2*)&XsT[kk][ty * 2];
            float4 wv = *(const float4*)&WsT[kk][tx * 4];
            float a2[2] = {av.x, av.y};
            float w4[4] = {wv.x, wv.y, wv.z, wv.w};
            #pragma unroll
            for (int i = 0; i < 2; i++)
                #pragma unroll
                for (int j = 0; j < 4; j++) acc[i][j] += a2[i] * w4[j];
        }
        __syncthreads();
    }

    // bias + per-CTA column partials
    int n = n0 + tx * 4;
    float4 bv = *(const float4*)&g_bcomb[n];
    float b4[4] = {bv.x, bv.y, bv.z, bv.w};
    float y[2][4];
    float cs[4] = {0.f,0.f,0.f,0.f}, cs2[4] = {0.f,0.f,0.f,0.f};
    #pragma unroll
    for (int i = 0; i < 2; i++)
        #pragma unroll
        for (int j = 0; j < 4; j++) {
            float v = acc[i][j] + b4[j];
            y[i][j] = v;
            cs[j] += v;
            cs2[j] += v * v;
        }
    #pragma unroll
    for (int j = 0; j < 4; j++) { shs[ty][tx*4+j] = cs[j]; shs2[ty][tx*4+j] = cs2[j]; }
    __syncthreads();
    #pragma unroll
    for (int off = 8; off >= 1; off >>= 1) {
        if (ty < off) {
            #pragma unroll
            for (int j = 0; j < 4; j++) {
                int c = tx * 4 + j;
                shs[ty][c] += shs[ty + off][c];
                shs2[ty][c] += shs2[ty + off][c];
            }
        }
        __syncthreads();
    }
    if (ty == 0) {
        #pragma unroll
        for (int j = 0; j < 4; j++) {
            int c = tx * 4 + j;
            g_part[blockIdx.y][0][n0 + c] = shs[0][c];
            g_part[blockIdx.y][1][n0 + c] = shs2[0][c];
        }
        __threadfence();   // writer-side fence before the CTA signals arrival
    }
    __syncthreads();

    // ---- grid barrier (64 CTAs, single wave) ----
    if (t == 0) {
        int gen = *((volatile int*)&g_gen);
        if (atomicAdd(&g_cnt, 1) == 63) {
            g_cnt = 0;
            __threadfence();
            *((volatile int*)&g_gen) = gen + 1;
        } else {
            while (*((volatile int*)&g_gen) == gen) { }
        }
        __threadfence();
    }
    __syncthreads();

    // ---- BN stats from all partials (L2 reads, bypass L1) ----
    if (t < Ec) {
        float S = 0.f, S2 = 0.f;
        #pragma unroll
        for (int c = 0; c < 32; c++) {
            S  += __ldcg(&g_part[c][0][t]);
            S2 += __ldcg(&g_part[c][1][t]);
        }
        float mean = S / (Bc * Lc);
        float var = S2 / (Bc * Lc) - mean * mean;
        float rs = rsqrtf(var + 1e-5f) * gamma[t];
        sscale[t] = rs;
        sshift[t] = beta[t] - mean * rs;
    }
    __syncthreads();

    // ---- apply BN + ReLU to register-resident y, write out ----
    float sc[4], sh[4];
    #pragma unroll
    for (int j = 0; j < 4; j++) { sc[j] = sscale[n0 + tx*4 + j - n0 + n - n0]; }
    // (simplify: direct indexing)
    #pragma unroll
    for (int j = 0; j < 4; j++) { sc[j] = sscale[n + j - n0 + n0 - 0 - (n - (n0 + tx*4))]; }
    // -- the above collapsed: channel index is just (n + j) - 0 within [0,128): n includes n0
    #pragma unroll
    for (int j = 0; j < 4; j++) { sc[j] = sscale[n + j]; sh[j] = sshift[n + j]; }
    #pragma unroll
    for (int i = 0; i < 2; i++) {
        int m = m0 + ty * 2 + i;
        float4 v = make_float4(fmaxf(y[i][0] * sc[0] + sh[0], 0.f),
                               fmaxf(y[i][1] * sc[1] + sh[1], 0.f),
                               fmaxf(y[i][2] * sc[2] + sh[2], 0.f),
                               fmaxf(y[i][3] * sc[3] + sh[3], 0.f));
        *(float4*)&out[(size_t)m * Ec + n] = v;
    }
}

extern "C" void kernel_launch(void* const* d_in, const int* in_sizes, int n_in,
                              void* d_out, int out_size)
{
    const float* UUMat   = (const float*)d_in[0];
    const float* DUMat   = (const float*)d_in[1];
    const float* TAMat   = (const float*)d_in[2];
    const float* CIMat   = (const float*)d_in[3];
    const float* uu_in_w = (const float*)d_in[4];
    const float* uu_in_b = (const float*)d_in[5];
    const float* uu_out_w= (const float*)d_in[6];
    const float* uu_out_b= (const float*)d_in[7];
    const float* ta_in_w = (const float*)d_in[8];
    const float* ta_in_b = (const float*)d_in[9];
    const float* ta_out_w= (const float*)d_in[10];
    const float* ta_out_b= (const float*)d_in[11];
    const float* du_in_w = (const float*)d_in[12];
    const float* du_in_b = (const float*)d_in[13];
    const float* du_out_w= (const float*)d_in[14];
    const float* du_out_b= (const float*)d_in[15];
    const float* dim_w   = (const float*)d_in[16];
    const float* dim_b   = (const float*)d_in[17];
    const float* bn_gamma= (const float*)d_in[18];
    const float* bn_beta = (const float*)d_in[19];
    float* out = (float*)d_out;

    prep_fused<<<1649, 256>>>(UUMat, DUMat, TAMat, CIMat,
                              uu_in_w, uu_in_b, ta_in_w, ta_in_b, du_in_w, du_in_b,
                              dim_w, dim_b, uu_out_w, uu_out_b,
                              ta_out_w, ta_out_b, du_out_w, du_out_b);

    attn_fused<<<1536, 128, NUc * 5 * sizeof(float4)>>>(uu_in_w);

    final_bn<<<dim3(2, 32), 256>>>(bn_gamma, bn_beta, out);
}